// round 16
// baseline (speedup 1.0000x reference)
#include <cuda_runtime.h>
#include <cuda_fp16.h>
#include <math.h>
#include <stdint.h>

#define BB 8
#define CC 256
#define NN 4096      // H*W
#define GG 32
#define CPG 8
#define EPSV 1e-5f

// ---------- SIMT GEMM tiling (R4 exact) --------------------------------------
#define BM 128
#define BN 256
#define BKH 32
#define PADH 8
#define ROWH (BKH + PADH)              // 40 half = 80 B
#define A_STG_H (BM * ROWH)
#define B_STG_H (BN * ROWH)
#define STG_H (A_STG_H + B_STG_H)      // 15360 half
#define SMEM_BYTES (2 * STG_H * 2)     // 61440 B
#define PV_SMEM (2 * STG_H * 2 + 512)  // + L[128] fp32

// ---------------- scratch (device globals) -----------------------------------
__device__ float  g_mean[BB * GG];
__device__ float  g_rstd[BB * GG];
__device__ float  g_wqe [3 * CC];                  // wq^T * W_k, scaled 1/16
__device__ float  g_W   [(size_t)BB * 3 * NN];     // wq_eff @ norm  [b][r][n]
__device__ __half g_normT[(size_t)BB * NN * CC];   // GN(x)^T [b][n][c]
__device__ __half g_val  [(size_t)BB * CC * NN];   // V' = (Wout*Wv) norm [c][n]
__device__ float  g_aoTf [(size_t)BB * NN * CC];   // out^T pre-bias [b][q][c]
__device__ __half g_wv2  [CC * CC];                // Wout @ Wv, fp16

// ---------------- 1. GroupNorm statistics ------------------------------------
__global__ void gn_stats(const float* __restrict__ x) {
    const int bg = blockIdx.x;
    const float* p = x + (size_t)bg * (CPG * NN);
    const int tid = threadIdx.x;
    float s = 0.f, s2 = 0.f;
    for (int i = tid; i < CPG * NN; i += 256) {
        float v = p[i];
        s += v; s2 += v * v;
    }
    __shared__ float sh[256], sh2[256];
    sh[tid] = s; sh2[tid] = s2;
    __syncthreads();
    for (int o = 128; o > 0; o >>= 1) {
        if (tid < o) { sh[tid] += sh[tid + o]; sh2[tid] += sh2[tid + o]; }
        __syncthreads();
    }
    if (tid == 0) {
        const float inv_n = 1.f / (CPG * NN);
        float m   = sh[0] * inv_n;
        float var = sh2[0] * inv_n - m * m;
        g_mean[bg] = m;
        g_rstd[bg] = rsqrtf(var + EPSV);
    }
}

// ---------------- 2a. wq_eff[r][c] = (1/16) sum_m wq[m][r] wkv[m][c] ---------
__global__ void prep_wq(const float* __restrict__ wq,
                        const float* __restrict__ wkv) {
    int c = threadIdx.x;                 // 256 threads, one block
    float s0 = 0.f, s1 = 0.f, s2 = 0.f;
    for (int m = 0; m < CC; m++) {
        float w = wkv[m * CC + c];       // key rows are wkv[0:256]
        s0 += wq[m * 3 + 0] * w;
        s1 += wq[m * 3 + 1] * w;
        s2 += wq[m * 3 + 2] * w;
    }
    g_wqe[c]           = 0.0625f * s0;
    g_wqe[CC + c]      = 0.0625f * s1;
    g_wqe[2 * CC + c]  = 0.0625f * s2;
}

// ---------------- 2b. W2[co][ci] = sum_m wout[co][m] wkv[CC+m][ci] -----------
__global__ void prep_w2(const float* __restrict__ wout,
                        const float* __restrict__ wkv) {
    int co = blockIdx.x, ci = threadIdx.x;
    float s = 0.f;
    for (int m = 0; m < CC; m++)
        s += wout[co * CC + m] * wkv[(CC + m) * CC + ci];
    g_wv2[co * CC + ci] = __float2half_rn(s);
}

// ---------------- 3. GroupNorm apply + transpose -> fp16 ---------------------
__global__ void __launch_bounds__(256) norm_t(const float* __restrict__ x,
                                              const float* __restrict__ gamma,
                                              const float* __restrict__ beta) {
    __shared__ float t[32][33];
    const int b  = blockIdx.z;
    const int n0 = blockIdx.x * 32, c0 = blockIdx.y * 32;
    const int tx = threadIdx.x, ty = threadIdx.y;
#pragma unroll
    for (int i = 0; i < 4; i++) {
        int c  = c0 + ty + i * 8;
        int bg = b * GG + (c >> 3);
        float sc = g_rstd[bg] * gamma[c];
        float sh = beta[c] - g_mean[bg] * sc;
        float v = x[((size_t)b * CC + c) * NN + n0 + tx];
        t[ty + i * 8][tx] = v * sc + sh;
    }
    __syncthreads();
#pragma unroll
    for (int i = 0; i < 4; i++) {
        int n = n0 + ty + i * 8;
        g_normT[((size_t)b * NN + n) * CC + c0 + tx] =
            __float2half_rn(t[tx][ty + i * 8]);
    }
}

// ---------------- 4. W[b][r][n] = sum_c wq_eff[r][c] * normT[b][n][c] --------
__global__ void __launch_bounds__(256) compute_W() {
    __shared__ float e0[CC], e1[CC], e2[CC];
    const int tid = threadIdx.x;
    e0[tid] = g_wqe[tid];
    e1[tid] = g_wqe[CC + tid];
    e2[tid] = g_wqe[2 * CC + tid];
    __syncthreads();

    const int b = blockIdx.y;
    const int n = blockIdx.x * 256 + tid;
    const uint4* nr = (const uint4*)(g_normT + ((size_t)b * NN + n) * CC);
    float w0 = 0.f, w1 = 0.f, w2 = 0.f;
#pragma unroll
    for (int i = 0; i < 32; i++) {
        uint4 u = nr[i];
        const __half2* h = (const __half2*)&u;
#pragma unroll
        for (int j = 0; j < 4; j++) {
            float2 f = __half22float2(h[j]);
            int c = i * 8 + j * 2;
            w0 += f.x * e0[c] + f.y * e0[c + 1];
            w1 += f.x * e1[c] + f.y * e1[c + 1];
            w2 += f.x * e2[c] + f.y * e2[c + 1];
        }
    }
    size_t base = (size_t)b * 3 * NN + n;
    g_W[base]          = w0;
    g_W[base + NN]     = w1;
    g_W[base + 2 * NN] = w2;
}

// ---------------- SIMT TN fp16 GEMM (used for V' projection, fp16 out) -------
#define CP16(d, s) asm volatile("cp.async.cg.shared.global [%0], [%1], 16;" :: "r"(d), "l"(s))

__global__ void __launch_bounds__(256) gemm_tn_f16(
    const __half* __restrict__ Ag, const __half* __restrict__ Bg,
    __half* __restrict__ Cg,
    int K, int ldc,
    size_t sA, size_t sB, size_t sC)
{
    extern __shared__ __half sm[];
    const int b = blockIdx.z;
    const __half* A = Ag + (size_t)b * sA;
    const __half* B = Bg + (size_t)b * sB;
    const int m0 = blockIdx.y * BM;
    const int n0 = blockIdx.x * BN;

    const int tid  = threadIdx.x;
    const int lane = tid & 31;
    const int warp = tid >> 5;
    const int wm = (warp & 1) * 64;
    const int wn = (warp >> 1) * 64;
    const int g = lane >> 2, t = lane & 3;

    const int r4 = tid >> 2;
    const int c8 = (tid & 3) * 8;
    const __half* Ap = A + (size_t)(m0 + r4) * K + c8;
    const __half* Bp = B + (size_t)(n0 + r4) * K + c8;
    const uint32_t sbase = (uint32_t)__cvta_generic_to_shared(sm);

#define ISSUE(s, ko)                                                          \
    do {                                                                      \
        uint32_t as_ = sbase + (uint32_t)(s) * (STG_H * 2);                   \
        uint32_t bs_ = as_ + A_STG_H * 2;                                     \
        const __half* ap_ = Ap + (ko);                                        \
        const __half* bp_ = Bp + (ko);                                        \
        CP16(as_ + (r4 * ROWH + c8) * 2,         ap_);                        \
        CP16(as_ + ((r4 + 64) * ROWH + c8) * 2,  ap_ + (size_t)64 * K);       \
        CP16(bs_ + (r4 * ROWH + c8) * 2,         bp_);                        \
        CP16(bs_ + ((r4 + 64) * ROWH + c8) * 2,  bp_ + (size_t)64 * K);       \
        CP16(bs_ + ((r4 + 128) * ROWH + c8) * 2, bp_ + (size_t)128 * K);      \
        CP16(bs_ + ((r4 + 192) * ROWH + c8) * 2, bp_ + (size_t)192 * K);      \
        asm volatile("cp.async.commit_group;");                               \
    } while (0)

    float acc[4][8][4];
#pragma unroll
    for (int mi = 0; mi < 4; mi++)
#pragma unroll
        for (int ni = 0; ni < 8; ni++)
#pragma unroll
            for (int r = 0; r < 4; r++) acc[mi][ni][r] = 0.f;

    const int iters = K / BKH;
    ISSUE(0, 0);
    ISSUE(1, BKH);
    asm volatile("cp.async.wait_group 1;");
    __syncthreads();

    for (int it = 0; it < iters; ++it) {
        const uint32_t* As = (const uint32_t*)(sm + (it & 1) * STG_H);
        const uint32_t* Bs = As + (A_STG_H >> 1);

#pragma unroll
        for (int kk = 0; kk < 2; kk++) {
            uint32_t af[4][4], bf[8][2];
#pragma unroll
            for (int mi = 0; mi < 4; mi++) {
                const uint32_t* p = As + (wm + mi * 16 + g) * (ROWH / 2) + kk * 8 + t;
                af[mi][0] = p[0];
                af[mi][1] = p[8 * (ROWH / 2)];
                af[mi][2] = p[4];
                af[mi][3] = p[8 * (ROWH / 2) + 4];
            }
#pragma unroll
            for (int ni = 0; ni < 8; ni++) {
                const uint32_t* p = Bs + (wn + ni * 8 + g) * (ROWH / 2) + kk * 8 + t;
                bf[ni][0] = p[0];
                bf[ni][1] = p[4];
            }
#pragma unroll
            for (int mi = 0; mi < 4; mi++)
#pragma unroll
                for (int ni = 0; ni < 8; ni++) {
                    float* d = acc[mi][ni];
                    asm volatile(
                        "mma.sync.aligned.m16n8k16.row.col.f32.f16.f16.f32 "
                        "{%0,%1,%2,%3}, {%4,%5,%6,%7}, {%8,%9}, {%0,%1,%2,%3};"
                        : "+f"(d[0]), "+f"(d[1]), "+f"(d[2]), "+f"(d[3])
                        : "r"(af[mi][0]), "r"(af[mi][1]), "r"(af[mi][2]), "r"(af[mi][3]),
                          "r"(bf[ni][0]), "r"(bf[ni][1]));
                }
        }
        __syncthreads();
        if (it + 2 < iters) {
            ISSUE(it & 1, (size_t)(it + 2) * BKH);
            asm volatile("cp.async.wait_group 1;");
        } else {
            asm volatile("cp.async.wait_group 0;");
        }
        __syncthreads();
    }

    __half* Cb = Cg + (size_t)b * sC;
#pragma unroll
    for (int mi = 0; mi < 4; mi++)
#pragma unroll
        for (int ni = 0; ni < 8; ni++) {
            int row = m0 + wm + mi * 16 + g;
            int col = n0 + wn + ni * 8 + t * 2;
            float* d = acc[mi][ni];
            *(__half2*)&Cb[(size_t)row * ldc + col] =
                __floats2half2_rn(d[0], d[1]);
            *(__half2*)&Cb[(size_t)(row + 8) * ldc + col] =
                __floats2half2_rn(d[2], d[3]);
        }
#undef ISSUE
}

// ---------------- fused exp-PV: aoTf[q][c] = (1/L) sum_n exp(s) V'[c][n] -----
// s[q][n] = q0 W0[n] + q1 W1[n] + q2 W2[n]; |s| small -> no max subtraction.
__global__ void __launch_bounds__(256) pv_fused(const float* __restrict__ quary) {
    extern __shared__ __half sm[];
    float* sL = (float*)(sm + 2 * STG_H);
    const int b = blockIdx.z;
    const int m0 = blockIdx.y * BM;

    const int tid  = threadIdx.x;
    const int lane = tid & 31;
    const int warp = tid >> 5;
    const int wm = (warp & 1) * 64;
    const int wn = (warp >> 1) * 64;
    const int g = lane >> 2, t = lane & 3;

    // B (V') cp.async mapping: rows = c, k = n, n0 = 0
    const int r4 = tid >> 2;
    const int c8 = (tid & 3) * 8;
    const __half* Bp = g_val + (size_t)b * CC * NN + (size_t)r4 * NN + c8;
    const uint32_t sbase = (uint32_t)__cvta_generic_to_shared(sm);

#define ISSUEB(s, ko)                                                         \
    do {                                                                      \
        uint32_t bs_ = sbase + (uint32_t)(s) * (STG_H * 2) + A_STG_H * 2;     \
        const __half* bp_ = Bp + (ko);                                        \
        CP16(bs_ + (r4 * ROWH + c8) * 2,         bp_);                        \
        CP16(bs_ + ((r4 + 64) * ROWH + c8) * 2,  bp_ + (size_t)64 * NN);      \
        CP16(bs_ + ((r4 + 128) * ROWH + c8) * 2, bp_ + (size_t)128 * NN);     \
        CP16(bs_ + ((r4 + 192) * ROWH + c8) * 2, bp_ + (size_t)192 * NN);     \
        asm volatile("cp.async.commit_group;");                               \
    } while (0)

    // A (P) producer mapping: row pr = tid>>1 (q), 16 cols starting pc
    const int pr = tid >> 1;
    const int pc = (tid & 1) * 16;
    const float* Wb = g_W + (size_t)b * 3 * NN;
    const float* qb = quary + (size_t)b * 3 * NN + m0 + pr;
    const float q0 = __ldg(qb);
    const float q1 = __ldg(qb + NN);
    const float q2 = __ldg(qb + 2 * NN);
    float lsum = 0.f;

#define PRODA(ci, s)                                                          \
    do {                                                                      \
        __half* arow = sm + (s) * STG_H + pr * ROWH + pc;                     \
        int nb = (ci) * BKH + pc;                                             \
        uint4 ou[2];                                                          \
        __half2* oh = (__half2*)ou;                                           \
        _Pragma("unroll")                                                     \
        for (int j4 = 0; j4 < 4; j4++) {                                      \
            float4 a0 = *(const float4*)&Wb[nb + j4 * 4];                     \
            float4 a1 = *(const float4*)&Wb[NN + nb + j4 * 4];                \
            float4 a2 = *(const float4*)&Wb[2 * NN + nb + j4 * 4];            \
            float e0_ = __expf(q0 * a0.x + q1 * a1.x + q2 * a2.x);            \
            float e1_ = __expf(q0 * a0.y + q1 * a1.y + q2 * a2.y);            \
            float e2_ = __expf(q0 * a0.z + q1 * a1.z + q2 * a2.z);            \
            float e3_ = __expf(q0 * a0.w + q1 * a1.w + q2 * a2.w);            \
            lsum += (e0_ + e1_) + (e2_ + e3_);                                \
            oh[j4 * 2]     = __floats2half2_rn(e0_, e1_);                     \
            oh[j4 * 2 + 1] = __floats2half2_rn(e2_, e3_);                     \
        }                                                                     \
        *(uint4*)arow       = ou[0];                                          \
        *(uint4*)(arow + 8) = ou[1];                                          \
    } while (0)

    float acc[4][8][4];
#pragma unroll
    for (int mi = 0; mi < 4; mi++)
#pragma unroll
        for (int ni = 0; ni < 8; ni++)
#pragma unroll
            for (int r = 0; r < 4; r++) acc[mi][ni][r] = 0.f;

    const int iters = NN / BKH;        // 128
    ISSUEB(0, 0);
    ISSUEB(1, BKH);
    PRODA(0, 0);
    asm volatile("cp.async.wait_group 1;");
    __syncthreads();

    for (int it = 0; it < iters; ++it) {
        const uint32_t* As = (const uint32_t*)(sm + (it & 1) * STG_H);
        const uint32_t* Bs = As + (A_STG_H >> 1);

#pragma unroll
        for (int kk = 0; kk < 2; kk++) {
            uint32_t af[4][4], bf[8][2];
#pragma unroll
            for (int mi = 0; mi < 4; mi++) {
                const uint32_t* p = As + (wm + mi * 16 + g) * (ROWH / 2) + kk * 8 + t;
                af[mi][0] = p[0];
                af[mi][1] = p[8 * (ROWH / 2)];
                af[mi][2] = p[4];
                af[mi][3] = p[8 * (ROWH / 2) + 4];
            }
#pragma unroll
            for (int ni = 0; ni < 8; ni++) {
                const uint32_t* p = Bs + (wn + ni * 8 + g) * (ROWH / 2) + kk * 8 + t;
                bf[ni][0] = p[0];
                bf[ni][1] = p[4];
            }
#pragma unroll
            for (int mi = 0; mi < 4; mi++)
#pragma unroll
                for (int ni = 0; ni < 8; ni++) {
                    float* d = acc[mi][ni];
                    asm volatile(
                        "mma.sync.aligned.m16n8k16.row.col.f32.f16.f16.f32 "
                        "{%0,%1,%2,%3}, {%4,%5,%6,%7}, {%8,%9}, {%0,%1,%2,%3};"
                        : "+f"(d[0]), "+f"(d[1]), "+f"(d[2]), "+f"(d[3])
                        : "r"(af[mi][0]), "r"(af[mi][1]), "r"(af[mi][2]), "r"(af[mi][3]),
                          "r"(bf[ni][0]), "r"(bf[ni][1]));
                }
        }
        // produce next A tile (other stage) while tensor pipe drains
        if (it + 1 < iters) PRODA(it + 1, (it + 1) & 1);
        __syncthreads();
        if (it + 2 < iters) {
            ISSUEB((it & 1), (size_t)(it + 2) * BKH);
            asm volatile("cp.async.wait_group 1;");
        } else {
            asm volatile("cp.async.wait_group 0;");
        }
        __syncthreads();
    }

    // combine row sums (threads 2r, 2r+1 are adjacent lanes)
    lsum += __shfl_xor_sync(0xffffffffu, lsum, 1);
    if ((tid & 1) == 0) sL[pr] = 1.f / lsum;
    __syncthreads();

    // epilogue: fp32 out^T tile [q][c], scaled by 1/L
    float* Cb = g_aoTf + (size_t)b * NN * CC;
#pragma unroll
    for (int mi = 0; mi < 4; mi++) {
        float i0 = sL[wm + mi * 16 + g];
        float i1 = sL[wm + mi * 16 + g + 8];
        int row = m0 + wm + mi * 16 + g;
#pragma unroll
        for (int ni = 0; ni < 8; ni++) {
            int col = wn + ni * 8 + t * 2;
            float* d = acc[mi][ni];
            *(float2*)&Cb[(size_t)row * CC + col] =
                make_float2(d[0] * i0, d[1] * i0);
            *(float2*)&Cb[(size_t)(row + 8) * CC + col] =
                make_float2(d[2] * i1, d[3] * i1);
        }
    }
#undef ISSUEB
#undef PRODA
}

// ---------------- final transpose + bias + residual --------------------------
__global__ void __launch_bounds__(256) out_tr(const float* __restrict__ xin,
                                              const float* __restrict__ bout,
                                              float* __restrict__ out) {
    __shared__ float t[32][33];
    const int b  = blockIdx.z;
    const int q0 = blockIdx.x * 32, c0 = blockIdx.y * 32;
    const int tx = threadIdx.x, ty = threadIdx.y;
#pragma unroll
    for (int i = 0; i < 4; i++) {
        int q = q0 + ty + i * 8;
        t[ty + i * 8][tx] = g_aoTf[((size_t)b * NN + q) * CC + c0 + tx];
    }
    __syncthreads();
#pragma unroll
    for (int i = 0; i < 4; i++) {
        int c = c0 + ty + i * 8;
        size_t o = ((size_t)b * CC + c) * NN + q0 + tx;
        out[o] = t[tx][ty + i * 8] + bout[c] + xin[o];
    }
}

// ---------------- launch ------------------------------------------------------
extern "C" void kernel_launch(void* const* d_in, const int* in_sizes, int n_in,
                              void* d_out, int out_size) {
    const float* input = (const float*)d_in[0];
    const float* quary = (const float*)d_in[1];
    const float* gw    = (const float*)d_in[2];
    const float* gb    = (const float*)d_in[3];
    const float* wq    = (const float*)d_in[4];
    const float* wkv   = (const float*)d_in[5];
    const float* wout  = (const float*)d_in[6];
    const float* bout  = (const float*)d_in[7];
    float* out = (float*)d_out;

    static int smem_set = 0;
    if (!smem_set) {
        cudaFuncSetAttribute(gemm_tn_f16,
                             cudaFuncAttributeMaxDynamicSharedMemorySize, SMEM_BYTES);
        cudaFuncSetAttribute(pv_fused,
                             cudaFuncAttributeMaxDynamicSharedMemorySize, PV_SMEM);
        smem_set = 1;
    }

    __half *p_normT, *p_val, *p_wv2;
    cudaGetSymbolAddress((void**)&p_normT, g_normT);
    cudaGetSymbolAddress((void**)&p_val,   g_val);
    cudaGetSymbolAddress((void**)&p_wv2,   g_wv2);

    const size_t sCN = (size_t)CC * NN;
    const size_t sNC = (size_t)NN * CC;

    gn_stats<<<BB * GG, 256>>>(input);
    prep_wq<<<1, 256>>>(wq, wkv);
    prep_w2<<<CC, 256>>>(wout, wkv);
    norm_t<<<dim3(NN / 32, CC / 32, BB), dim3(32, 8)>>>(input, gw, gb);

    // W = wq_eff @ norm  (fp32, [b][3][n])
    compute_W<<<dim3(NN / 256, BB), 256>>>();

    // V' = (Wout Wv) @ norm : fp16 [c][n]
    gemm_tn_f16<<<dim3(NN / BN, CC / BM, BB), 256, SMEM_BYTES>>>(
        p_wv2, p_normT, p_val, CC, NN, 0, sNC, sCN);

    // fused exp-PV -> aoTf fp32 [q][c]
    pv_fused<<<dim3(1, NN / BM, BB), 256, PV_SMEM>>>(quary);

    // out = aoTf^T + bias + input
    out_tr<<<dim3(NN / 32, CC / 32, BB), dim3(32, 8)>>>(input, bout, out);
}

// round 17
// speedup vs baseline: 1.0022x; 1.0022x over previous
#include <cuda_runtime.h>
#include <cuda_fp16.h>
#include <math.h>
#include <stdint.h>

#define BB 8
#define CC 256
#define NN 4096      // H*W
#define GG 32
#define CPG 8
#define EPSV 1e-5f

// ---------- SIMT GEMM tiling (R4 exact) --------------------------------------
#define BM 128
#define BN 256
#define BKH 32
#define PADH 8
#define ROWH (BKH + PADH)              // 40 half = 80 B
#define A_STG_H (BM * ROWH)
#define B_STG_H (BN * ROWH)
#define STG_H (A_STG_H + B_STG_H)      // 15360 half
#define SMEM_BYTES (2 * STG_H * 2)     // 61440 B

#define QK_SMEM (3 * NN * 4 + 128)     // W tile + qv + red

// ---------------- scratch (device globals) -----------------------------------
__device__ float  g_mean[BB * GG];
__device__ float  g_rstd[BB * GG];
__device__ float  g_wqe [3 * CC];                  // wq^T * W_k, scaled 1/16
__device__ float  g_W   [(size_t)BB * 3 * NN];     // wq_eff @ norm  [b][r][n]
__device__ __half g_normT[(size_t)BB * NN * CC];   // GN(x)^T [b][n][c]
__device__ __half g_val  [(size_t)BB * CC * NN];   // V' = (Wout*Wv) norm [c][n]
__device__ __half g_attn [(size_t)BB * NN * NN];   // P    [b][m][n]  256 MB
__device__ float  g_aoTf [(size_t)BB * NN * CC];   // out^T pre-bias [b][q][c]
__device__ __half g_wv2  [CC * CC];                // Wout @ Wv, fp16

// ---------------- 1. GroupNorm statistics ------------------------------------
__global__ void gn_stats(const float* __restrict__ x) {
    const int bg = blockIdx.x;
    const float* p = x + (size_t)bg * (CPG * NN);
    const int tid = threadIdx.x;
    float s = 0.f, s2 = 0.f;
    for (int i = tid; i < CPG * NN; i += 256) {
        float v = p[i];
        s += v; s2 += v * v;
    }
    __shared__ float sh[256], sh2[256];
    sh[tid] = s; sh2[tid] = s2;
    __syncthreads();
    for (int o = 128; o > 0; o >>= 1) {
        if (tid < o) { sh[tid] += sh[tid + o]; sh2[tid] += sh2[tid + o]; }
        __syncthreads();
    }
    if (tid == 0) {
        const float inv_n = 1.f / (CPG * NN);
        float m   = sh[0] * inv_n;
        float var = sh2[0] * inv_n - m * m;
        g_mean[bg] = m;
        g_rstd[bg] = rsqrtf(var + EPSV);
    }
}

// ---------------- 2a. wq_eff[r][c] = (1/16) sum_m wq[m][r] wkv[m][c] ---------
__global__ void prep_wq(const float* __restrict__ wq,
                        const float* __restrict__ wkv) {
    int c = threadIdx.x;                 // 256 threads, one block
    float s0 = 0.f, s1 = 0.f, s2 = 0.f;
    for (int m = 0; m < CC; m++) {
        float w = wkv[m * CC + c];       // key rows are wkv[0:256]
        s0 += wq[m * 3 + 0] * w;
        s1 += wq[m * 3 + 1] * w;
        s2 += wq[m * 3 + 2] * w;
    }
    g_wqe[c]           = 0.0625f * s0;
    g_wqe[CC + c]      = 0.0625f * s1;
    g_wqe[2 * CC + c]  = 0.0625f * s2;
}

// ---------------- 2b. W2[co][ci] = sum_m wout[co][m] wkv[CC+m][ci] -----------
__global__ void prep_w2(const float* __restrict__ wout,
                        const float* __restrict__ wkv) {
    int co = blockIdx.x, ci = threadIdx.x;
    float s = 0.f;
    for (int m = 0; m < CC; m++)
        s += wout[co * CC + m] * wkv[(CC + m) * CC + ci];
    g_wv2[co * CC + ci] = __float2half_rn(s);
}

// ---------------- 3. GroupNorm apply + transpose -> fp16 ---------------------
__global__ void __launch_bounds__(256) norm_t(const float* __restrict__ x,
                                              const float* __restrict__ gamma,
                                              const float* __restrict__ beta) {
    __shared__ float t[32][33];
    const int b  = blockIdx.z;
    const int n0 = blockIdx.x * 32, c0 = blockIdx.y * 32;
    const int tx = threadIdx.x, ty = threadIdx.y;
#pragma unroll
    for (int i = 0; i < 4; i++) {
        int c  = c0 + ty + i * 8;
        int bg = b * GG + (c >> 3);
        float sc = g_rstd[bg] * gamma[c];
        float sh = beta[c] - g_mean[bg] * sc;
        float v = x[((size_t)b * CC + c) * NN + n0 + tx];
        t[ty + i * 8][tx] = v * sc + sh;
    }
    __syncthreads();
#pragma unroll
    for (int i = 0; i < 4; i++) {
        int n = n0 + ty + i * 8;
        g_normT[((size_t)b * NN + n) * CC + c0 + tx] =
            __float2half_rn(t[tx][ty + i * 8]);
    }
}

// ---------------- 4. W[b][r][n] = sum_c wq_eff[r][c] * normT[b][n][c] --------
__global__ void __launch_bounds__(256) compute_W() {
    __shared__ float e0[CC], e1[CC], e2[CC];
    const int tid = threadIdx.x;
    e0[tid] = g_wqe[tid];
    e1[tid] = g_wqe[CC + tid];
    e2[tid] = g_wqe[2 * CC + tid];
    __syncthreads();

    const int b = blockIdx.y;
    const int n = blockIdx.x * 256 + tid;
    const uint4* nr = (const uint4*)(g_normT + ((size_t)b * NN + n) * CC);
    float w0 = 0.f, w1 = 0.f, w2 = 0.f;
#pragma unroll
    for (int i = 0; i < 32; i++) {
        uint4 u = nr[i];
        const __half2* h = (const __half2*)&u;
#pragma unroll
        for (int j = 0; j < 4; j++) {
            float2 f = __half22float2(h[j]);
            int c = i * 8 + j * 2;
            w0 += f.x * e0[c] + f.y * e0[c + 1];
            w1 += f.x * e1[c] + f.y * e1[c + 1];
            w2 += f.x * e2[c] + f.y * e2[c + 1];
        }
    }
    size_t base = (size_t)b * 3 * NN + n;
    g_W[base]          = w0;
    g_W[base + NN]     = w1;
    g_W[base + 2 * NN] = w2;
}

// ---------------- 5. fused S + softmax -> P (fp16) [R14 exact] ---------------
__global__ void __launch_bounds__(256) qk_softmax(const float* __restrict__ quary) {
    extern __shared__ float sW[];                 // [3*NN] + qv[24] + red[8]
    float* qv  = sW + 3 * NN;
    float* red = qv + 24;
    const int tid = threadIdx.x;
    const int lane = tid & 31, wid = tid >> 5;
    const int b  = blockIdx.y;
    const int m0 = blockIdx.x * 8;

    const float4* Wb = (const float4*)(g_W + (size_t)b * 3 * NN);
#pragma unroll
    for (int i = 0; i < 12; i++)
        ((float4*)sW)[tid + i * 256] = Wb[tid + i * 256];
    if (tid < 24) {
        int row = tid / 3, r = tid % 3;
        qv[tid] = quary[((size_t)b * 3 + r) * NN + m0 + row];
    }
    __syncthreads();

    for (int row = 0; row < 8; row++) {
        float q0 = qv[row * 3], q1 = qv[row * 3 + 1], q2 = qv[row * 3 + 2];
        float e[16];
        float l = 0.f;
#pragma unroll
        for (int i = 0; i < 8; i++) {
            int c0 = 2 * tid + i * 512;
            float s0 = q0 * sW[c0]     + q1 * sW[NN + c0]     + q2 * sW[2 * NN + c0];
            float s1 = q0 * sW[c0 + 1] + q1 * sW[NN + c0 + 1] + q2 * sW[2 * NN + c0 + 1];
            float v0 = __expf(s0), v1 = __expf(s1);
            e[2 * i] = v0; e[2 * i + 1] = v1;
            l += v0 + v1;
        }
#pragma unroll
        for (int o = 16; o > 0; o >>= 1)
            l += __shfl_xor_sync(0xffffffffu, l, o);
        if (lane == 0) red[wid] = l;
        __syncthreads();
        l = 0.f;
#pragma unroll
        for (int i = 0; i < 8; i++) l += red[i];
        float inv = 1.f / l;

        __half2* P = (__half2*)(g_attn + ((size_t)b * NN + m0 + row) * NN);
#pragma unroll
        for (int i = 0; i < 8; i++)
            P[tid + i * 256] = __floats2half2_rn(e[2 * i] * inv, e[2 * i + 1] * inv);
        __syncthreads();
    }
}

// ---------------- SIMT TN fp16 GEMM (mode 0: fp32 out, mode 1: fp16 out) -----
#define CP16(d, s) asm volatile("cp.async.cg.shared.global [%0], [%1], 16;" :: "r"(d), "l"(s))

__global__ void __launch_bounds__(256) gemm_tn_f16(
    const __half* __restrict__ Ag, const __half* __restrict__ Bg,
    void* __restrict__ Cg,
    int K, int ldc, int mode,
    size_t sA, size_t sB, size_t sC)
{
    extern __shared__ __half sm[];
    const int b = blockIdx.z;
    const __half* A = Ag + (size_t)b * sA;
    const __half* B = Bg + (size_t)b * sB;
    const int m0 = blockIdx.y * BM;
    const int n0 = blockIdx.x * BN;

    const int tid  = threadIdx.x;
    const int lane = tid & 31;
    const int warp = tid >> 5;
    const int wm = (warp & 1) * 64;
    const int wn = (warp >> 1) * 64;
    const int g = lane >> 2, t = lane & 3;

    const int r4 = tid >> 2;
    const int c8 = (tid & 3) * 8;
    const __half* Ap = A + (size_t)(m0 + r4) * K + c8;
    const __half* Bp = B + (size_t)(n0 + r4) * K + c8;
    const uint32_t sbase = (uint32_t)__cvta_generic_to_shared(sm);

#define ISSUE(s, ko)                                                          \
    do {                                                                      \
        uint32_t as_ = sbase + (uint32_t)(s) * (STG_H * 2);                   \
        uint32_t bs_ = as_ + A_STG_H * 2;                                     \
        const __half* ap_ = Ap + (ko);                                        \
        const __half* bp_ = Bp + (ko);                                        \
        CP16(as_ + (r4 * ROWH + c8) * 2,         ap_);                        \
        CP16(as_ + ((r4 + 64) * ROWH + c8) * 2,  ap_ + (size_t)64 * K);       \
        CP16(bs_ + (r4 * ROWH + c8) * 2,         bp_);                        \
        CP16(bs_ + ((r4 + 64) * ROWH + c8) * 2,  bp_ + (size_t)64 * K);       \
        CP16(bs_ + ((r4 + 128) * ROWH + c8) * 2, bp_ + (size_t)128 * K);      \
        CP16(bs_ + ((r4 + 192) * ROWH + c8) * 2, bp_ + (size_t)192 * K);      \
        asm volatile("cp.async.commit_group;");                               \
    } while (0)

    float acc[4][8][4];
#pragma unroll
    for (int mi = 0; mi < 4; mi++)
#pragma unroll
        for (int ni = 0; ni < 8; ni++)
#pragma unroll
            for (int r = 0; r < 4; r++) acc[mi][ni][r] = 0.f;

    const int iters = K / BKH;
    ISSUE(0, 0);
    ISSUE(1, BKH);
    asm volatile("cp.async.wait_group 1;");
    __syncthreads();

    for (int it = 0; it < iters; ++it) {
        const uint32_t* As = (const uint32_t*)(sm + (it & 1) * STG_H);
        const uint32_t* Bs = As + (A_STG_H >> 1);

#pragma unroll
        for (int kk = 0; kk < 2; kk++) {
            uint32_t af[4][4], bf[8][2];
#pragma unroll
            for (int mi = 0; mi < 4; mi++) {
                const uint32_t* p = As + (wm + mi * 16 + g) * (ROWH / 2) + kk * 8 + t;
                af[mi][0] = p[0];
                af[mi][1] = p[8 * (ROWH / 2)];
                af[mi][2] = p[4];
                af[mi][3] = p[8 * (ROWH / 2) + 4];
            }
#pragma unroll
            for (int ni = 0; ni < 8; ni++) {
                const uint32_t* p = Bs + (wn + ni * 8 + g) * (ROWH / 2) + kk * 8 + t;
                bf[ni][0] = p[0];
                bf[ni][1] = p[4];
            }
#pragma unroll
            for (int mi = 0; mi < 4; mi++)
#pragma unroll
                for (int ni = 0; ni < 8; ni++) {
                    float* d = acc[mi][ni];
                    asm volatile(
                        "mma.sync.aligned.m16n8k16.row.col.f32.f16.f16.f32 "
                        "{%0,%1,%2,%3}, {%4,%5,%6,%7}, {%8,%9}, {%0,%1,%2,%3};"
                        : "+f"(d[0]), "+f"(d[1]), "+f"(d[2]), "+f"(d[3])
                        : "r"(af[mi][0]), "r"(af[mi][1]), "r"(af[mi][2]), "r"(af[mi][3]),
                          "r"(bf[ni][0]), "r"(bf[ni][1]));
                }
        }
        __syncthreads();
        if (it + 2 < iters) {
            ISSUE(it & 1, (size_t)(it + 2) * BKH);
            asm volatile("cp.async.wait_group 1;");
        } else {
            asm volatile("cp.async.wait_group 0;");
        }
        __syncthreads();
    }

    if (mode == 0) {
        float* Cb = (float*)Cg + (size_t)b * sC;
#pragma unroll
        for (int mi = 0; mi < 4; mi++)
#pragma unroll
            for (int ni = 0; ni < 8; ni++) {
                int row = m0 + wm + mi * 16 + g;
                int col = n0 + wn + ni * 8 + t * 2;
                float* d = acc[mi][ni];
                *(float2*)&Cb[(size_t)row * ldc + col]       = make_float2(d[0], d[1]);
                *(float2*)&Cb[(size_t)(row + 8) * ldc + col] = make_float2(d[2], d[3]);
            }
    } else {
        __half* Cb = (__half*)Cg + (size_t)b * sC;
#pragma unroll
        for (int mi = 0; mi < 4; mi++)
#pragma unroll
            for (int ni = 0; ni < 8; ni++) {
                int row = m0 + wm + mi * 16 + g;
                int col = n0 + wn + ni * 8 + t * 2;
                float* d = acc[mi][ni];
                *(__half2*)&Cb[(size_t)row * ldc + col] =
                    __floats2half2_rn(d[0], d[1]);
                *(__half2*)&Cb[(size_t)(row + 8) * ldc + col] =
                    __floats2half2_rn(d[2], d[3]);
            }
    }
#undef ISSUE
}

// ---------------- final transpose + bias + residual --------------------------
__global__ void __launch_bounds__(256) out_tr(const float* __restrict__ xin,
                                              const float* __restrict__ bout,
                                              float* __restrict__ out) {
    __shared__ float t[32][33];
    const int b  = blockIdx.z;
    const int q0 = blockIdx.x * 32, c0 = blockIdx.y * 32;
    const int tx = threadIdx.x, ty = threadIdx.y;
#pragma unroll
    for (int i = 0; i < 4; i++) {
        int q = q0 + ty + i * 8;
        t[ty + i * 8][tx] = g_aoTf[((size_t)b * NN + q) * CC + c0 + tx];
    }
    __syncthreads();
#pragma unroll
    for (int i = 0; i < 4; i++) {
        int c = c0 + ty + i * 8;
        size_t o = ((size_t)b * CC + c) * NN + q0 + tx;
        out[o] = t[tx][ty + i * 8] + bout[c] + xin[o];
    }
}

// ---------------- launch ------------------------------------------------------
extern "C" void kernel_launch(void* const* d_in, const int* in_sizes, int n_in,
                              void* d_out, int out_size) {
    const float* input = (const float*)d_in[0];
    const float* quary = (const float*)d_in[1];
    const float* gw    = (const float*)d_in[2];
    const float* gb    = (const float*)d_in[3];
    const float* wq    = (const float*)d_in[4];
    const float* wkv   = (const float*)d_in[5];
    const float* wout  = (const float*)d_in[6];
    const float* bout  = (const float*)d_in[7];
    float* out = (float*)d_out;

    static int smem_set = 0;
    if (!smem_set) {
        cudaFuncSetAttribute(gemm_tn_f16,
                             cudaFuncAttributeMaxDynamicSharedMemorySize, SMEM_BYTES);
        cudaFuncSetAttribute(qk_softmax,
                             cudaFuncAttributeMaxDynamicSharedMemorySize, QK_SMEM);
        smem_set = 1;
    }

    __half *p_normT, *p_val, *p_attn, *p_wv2;
    float *p_aoTf;
    cudaGetSymbolAddress((void**)&p_normT, g_normT);
    cudaGetSymbolAddress((void**)&p_val,   g_val);
    cudaGetSymbolAddress((void**)&p_attn,  g_attn);
    cudaGetSymbolAddress((void**)&p_aoTf,  g_aoTf);
    cudaGetSymbolAddress((void**)&p_wv2,   g_wv2);

    const size_t sCN  = (size_t)CC * NN;
    const size_t sNC  = (size_t)NN * CC;
    const size_t sNNb = (size_t)NN * NN;

    gn_stats<<<BB * GG, 256>>>(input);
    prep_wq<<<1, 256>>>(wq, wkv);
    prep_w2<<<CC, 256>>>(wout, wkv);
    norm_t<<<dim3(NN / 32, CC / 32, BB), dim3(32, 8)>>>(input, gw, gb);

    // W = wq_eff @ norm  (fp32, [b][3][n])
    compute_W<<<dim3(NN / 256, BB), 256>>>();

    // V' = (Wout Wv) @ norm : fp16 [c][n]
    gemm_tn_f16<<<dim3(NN / BN, CC / BM, BB), 256, SMEM_BYTES>>>(
        p_wv2, p_normT, p_val, CC, NN, 1, 0, sNC, sCN);

    // P = softmax(quary^T W) fused, fp16 [m][n]
    qk_softmax<<<dim3(NN / 8, BB), 256, QK_SMEM>>>(quary);

    // aoTf[q][c] = P @ V'^T : fp32 direct (W_out pre-folded into V')
    gemm_tn_f16<<<dim3(CC / BN, NN / BM, BB), 256, SMEM_BYTES>>>(
        p_attn, p_val, p_aoTf, NN, CC, 0, sNNb, sCN, sNC);

    // out = aoTf^T + bias + input
    out_tr<<<dim3(NN / 32, CC / 32, BB), dim3(32, 8)>>>(input, bout, out);
}